// round 4
// baseline (speedup 1.0000x reference)
#include <cuda_runtime.h>

#define NP    64                 // patch size
#define CH    4                  // channels
#define PAD   192                // canvas
#define TPB   384
#define PLW   72                 // padded plane width  (4 left, 4 right)
#define PLH   66                 // padded plane height (1 top, 1 bottom)
#define PLANE (PLW*PLH)          // 4752 floats per channel plane
#define SMF   (CH*PLANE)         // 19008 floats = 76,032 B
#define QROWS 48                 // rows per block (quarter canvas)
#define QPB   (QROWS*(PAD/4))    // quads per block = 48*48 = 2304
#define ITER  (QPB/TPB)          // 6

// out[b,y,x] = sum_c bilinear(patch_c centered, y-64-dy_c, x-64-dx_c), zero fill.
// For integer (x,y): floor(y-64-dy) = y + floor(-64-dy); fractional bilinear
// weights are constant per (b,c). Patch planes staged channel-major in smem
// with a zero border so the 5x2 tap reads need no predicates.
__global__ __launch_bounds__(TPB, 3)
void reassemble_pad_kernel(const float* __restrict__ patches,
                           const float* __restrict__ pos,
                           float* __restrict__ out)
{
    extern __shared__ float sm[];        // CH planes of [PLH][PLW], zero border
    const int b    = blockIdx.x;
    const int tid  = threadIdx.x;

    // ---- zero all planes (covers the borders) ----
    float4* smv = reinterpret_cast<float4*>(sm);
    for (int i = tid; i < SMF / 4; i += TPB)
        smv[i] = make_float4(0.f, 0.f, 0.f, 0.f);
    __syncthreads();

    // ---- fill interior: (64,64,4) pixel-major -> 4 channel planes ----
    const float4* pin = reinterpret_cast<const float4*>(patches + (size_t)b * NP * NP * CH);
    for (int idx = tid; idx < NP * NP; idx += TPB) {
        const float4 v = pin[idx];
        const int py = idx >> 6;
        const int px = idx & 63;
        const int o  = (py + 1) * PLW + (px + 4);
        sm[0 * PLANE + o] = v.x;
        sm[1 * PLANE + o] = v.y;
        sm[2 * PLANE + o] = v.z;
        sm[3 * PLANE + o] = v.w;
    }

    // ---- per-channel integer offsets + constant bilinear weights ----
    int   oxc[CH], oyc[CH];
    float w00[CH], w01[CH], w10[CH], w11[CH];
    const float* pb_pos = pos + (size_t)b * 2 * CH;
    #pragma unroll
    for (int c = 0; c < CH; c++) {
        const float dx = __ldg(pb_pos + c);
        const float dy = __ldg(pb_pos + CH + c);
        const float fx = -64.0f - dx;
        const float fy = -64.0f - dy;
        const float flx = floorf(fx), fly = floorf(fy);
        oxc[c] = (int)flx;
        oyc[c] = (int)fly;
        const float wx = fx - flx, wy = fy - fly;
        w00[c] = (1.0f - wx) * (1.0f - wy);
        w01[c] = wx * (1.0f - wy);
        w10[c] = (1.0f - wx) * wy;
        w11[c] = wx * wy;
    }
    __syncthreads();

    // ---- phase 2: quarter canvas; 8 quad-rows of 48 quads per iteration ----
    const int qcol = tid % (PAD / 4);            // fixed quad column 0..47
    const int x0   = qcol * 4;
    int y = blockIdx.y * QROWS + tid / (PAD / 4);
    float* ob = out + (size_t)b * PAD * PAD;

    #pragma unroll
    for (int q = 0; q < ITER; q++, y += (TPB / (PAD / 4))) {
        float a0 = 0.f, a1 = 0.f, a2 = 0.f, a3 = 0.f;

        #pragma unroll
        for (int c = 0; c < CH; c++) {
            const int iy = y + oyc[c];               // top tap row (patch coords)
            if ((unsigned)(iy + 1) > 64u) continue;  // iy outside [-1, 63]
            const int ix = x0 + oxc[c];              // left tap col of pixel 0
            if ((unsigned)(ix + 4) > 67u) continue;  // ix outside [-4, 63]

            const float* r0 = sm + c * PLANE + (iy + 1) * PLW + (ix + 4);
            const float* r1 = r0 + PLW;
            const float vt0 = r0[0], vt1 = r0[1], vt2 = r0[2], vt3 = r0[3], vt4 = r0[4];
            const float vb0 = r1[0], vb1 = r1[1], vb2 = r1[2], vb3 = r1[3], vb4 = r1[4];

            const float W00 = w00[c], W01 = w01[c], W10 = w10[c], W11 = w11[c];
            a0 += vt0 * W00 + vt1 * W01 + vb0 * W10 + vb1 * W11;
            a1 += vt1 * W00 + vt2 * W01 + vb1 * W10 + vb2 * W11;
            a2 += vt2 * W00 + vt3 * W01 + vb2 * W10 + vb3 * W11;
            a3 += vt3 * W00 + vt4 * W01 + vb3 * W10 + vb4 * W11;
        }

        float4 o4; o4.x = a0; o4.y = a1; o4.z = a2; o4.w = a3;
        *reinterpret_cast<float4*>(ob + (size_t)y * PAD + x0) = o4;
    }
}

extern "C" void kernel_launch(void* const* d_in, const int* in_sizes, int n_in,
                              void* d_out, int out_size) {
    const float* patches = (const float*)d_in[0];   // (B, 64, 64, 4) fp32
    const float* pos     = (const float*)d_in[1];   // (B, 1, 2, 4)  fp32
    float* out           = (float*)d_out;           // (B, 192, 192, 1) fp32

    const int B = out_size / (PAD * PAD);           // 512
    const int smem_bytes = SMF * sizeof(float);     // 76,032 B
    static bool attr_set = false;
    if (!attr_set) {
        cudaFuncSetAttribute(reassemble_pad_kernel,
                             cudaFuncAttributeMaxDynamicSharedMemorySize, smem_bytes);
        attr_set = true;
    }
    dim3 grid(B, 4);                                // quarter-canvas blocks
    reassemble_pad_kernel<<<grid, TPB, smem_bytes>>>(patches, pos, out);
}

// round 5
// speedup vs baseline: 1.0710x; 1.0710x over previous
#include <cuda_runtime.h>

#define NP    64                 // patch size
#define CH    4                  // channels
#define PAD   192                // canvas
#define TPB   512
#define PLW   76                 // G plane width  (pad: left 3+shift, right zeros)
#define PLH   65                 // G rows: iy+1 in [0,64]
#define PLANE (PLW*PLH)          // 4940 floats (16B-aligned: 4940 % 4 == 0)
#define SMF   (CH*PLANE)         // 19760 floats = 79,040 B
#define GPOS  (65*65)            // valid G positions per channel

// out[b,y,x] = sum_c bilinear(patch_c centered, y-64-dy_c, x-64-dx_c), zero fill.
// Weights are constant per (b,c) => out(y,x) = G_c[y+oyc][x+oxc] where
// G_c = 2x2 correlation of patch_c with the 4 bilinear weights. G is
// precomputed into smem once; eval is one aligned LDS.128 per channel-hit.
__global__ __launch_bounds__(TPB, 2)
void reassemble_conv_kernel(const float* __restrict__ patches,
                            const float* __restrict__ pos,
                            float* __restrict__ out)
{
    extern __shared__ float sm[];        // CH planes of [PLH][PLW]
    const int b   = blockIdx.x;
    const int tid = threadIdx.x;

    // ---- per-channel constants ----
    int   oxc[CH], oyc[CH], shf[CH];
    float w00[CH], w01[CH], w10[CH], w11[CH];
    const float* pb_pos = pos + (size_t)b * 2 * CH;
    #pragma unroll
    for (int c = 0; c < CH; c++) {
        const float dx = __ldg(pb_pos + c);
        const float dy = __ldg(pb_pos + CH + c);
        const float fx = -64.0f - dx;
        const float fy = -64.0f - dy;
        const float flx = floorf(fx), fly = floorf(fy);
        oxc[c] = (int)flx;
        oyc[c] = (int)fly;
        shf[c] = (4 - (oxc[c] & 3)) & 3;           // (oxc+shf) % 4 == 0
        const float wx = fx - flx, wy = fy - fly;
        w00[c] = (1.0f - wx) * (1.0f - wy);
        w01[c] = wx * (1.0f - wy);
        w10[c] = (1.0f - wx) * wy;
        w11[c] = wx * wy;
    }

    // ---- zero all planes (borders / padding) ----
    float4* smv = reinterpret_cast<float4*>(sm);
    #pragma unroll
    for (int i = tid; i < SMF / 4; i += TPB)
        smv[i] = make_float4(0.f, 0.f, 0.f, 0.f);
    __syncthreads();

    // ---- build G planes directly from global (no P staging) ----
    // G position: gy = iy+1 in [0,64], gxi = ix+1 in [0,64].
    const float4* pin = reinterpret_cast<const float4*>(patches + (size_t)b * NP * NP * CH);
    for (int idx = tid; idx < GPOS; idx += TPB) {
        const int gy  = idx / 65;
        const int gxi = idx - gy * 65;
        const int iy  = gy - 1;             // top tap row
        const int ix  = gxi - 1;            // left tap col

        const bool r0 = (gy >= 1), r1 = (gy <= 63);
        const bool c0 = (gxi >= 1), c1 = (gxi <= 63);
        const float4 z = make_float4(0.f, 0.f, 0.f, 0.f);
        const float4 t00 = (r0 && c0) ? __ldg(pin + iy * NP + ix)     : z;
        const float4 t01 = (r0 && c1) ? __ldg(pin + iy * NP + ix + 1) : z;
        const float4 t10 = (r1 && c0) ? __ldg(pin + gy * NP + ix)     : z;
        const float4 t11 = (r1 && c1) ? __ldg(pin + gy * NP + ix + 1) : z;

        sm[0 * PLANE + gy * PLW + gxi + 3 + shf[0]] =
            t00.x * w00[0] + t01.x * w01[0] + t10.x * w10[0] + t11.x * w11[0];
        sm[1 * PLANE + gy * PLW + gxi + 3 + shf[1]] =
            t00.y * w00[1] + t01.y * w01[1] + t10.y * w10[1] + t11.y * w11[1];
        sm[2 * PLANE + gy * PLW + gxi + 3 + shf[2]] =
            t00.z * w00[2] + t01.z * w01[2] + t10.z * w10[2] + t11.z * w11[2];
        sm[3 * PLANE + gy * PLW + gxi + 3 + shf[3]] =
            t00.w * w00[3] + t01.w * w01[3] + t10.w * w10[3] + t11.w * w11[3];
    }
    __syncthreads();

    // ---- eval: half canvas, 4 consecutive x per thread, float4 store ----
    const int ybase = blockIdx.y * (PAD / 2);
    float* ob = out + (size_t)b * PAD * PAD;

    #pragma unroll
    for (int q = 0; q < (PAD / 2) * (PAD / 4) / TPB; q++) {   // 9 iterations
        const int p   = q * TPB + tid;                        // 0..4607
        const int row = p / (PAD / 4);                        // /48
        const int x0  = (p - row * (PAD / 4)) * 4;
        const int y   = ybase + row;

        float a0 = 0.f, a1 = 0.f, a2 = 0.f, a3 = 0.f;

        #pragma unroll
        for (int c = 0; c < CH; c++) {
            const int iy = y + oyc[c];
            if ((unsigned)(iy + 1) > 64u) continue;           // iy outside [-1,63]
            const int ix0 = x0 + oxc[c];
            if ((unsigned)(ix0 + 4) > 67u) continue;          // ix0 outside [-4,63]

            const float4 g = *reinterpret_cast<const float4*>(
                sm + c * PLANE + (iy + 1) * PLW + (ix0 + 4 + shf[c]));
            a0 += g.x; a1 += g.y; a2 += g.z; a3 += g.w;
        }

        float4 o4; o4.x = a0; o4.y = a1; o4.z = a2; o4.w = a3;
        *reinterpret_cast<float4*>(ob + (size_t)y * PAD + x0) = o4;
    }
}

extern "C" void kernel_launch(void* const* d_in, const int* in_sizes, int n_in,
                              void* d_out, int out_size) {
    const float* patches = (const float*)d_in[0];   // (B, 64, 64, 4) fp32
    const float* pos     = (const float*)d_in[1];   // (B, 1, 2, 4)  fp32
    float* out           = (float*)d_out;           // (B, 192, 192, 1) fp32

    const int B = out_size / (PAD * PAD);           // 512
    const int smem_bytes = SMF * sizeof(float);     // 79,040 B
    static bool attr_set = false;
    if (!attr_set) {
        cudaFuncSetAttribute(reassemble_conv_kernel,
                             cudaFuncAttributeMaxDynamicSharedMemorySize, smem_bytes);
        attr_set = true;
    }
    dim3 grid(B, 2);                                // half-canvas blocks
    reassemble_conv_kernel<<<grid, TPB, smem_bytes>>>(patches, pos, out);
}

// round 6
// speedup vs baseline: 1.4110x; 1.3174x over previous
#include <cuda_runtime.h>

#define NP    64                 // patch size
#define CH    4                  // channels
#define PAD   192                // canvas
#define TPB   512
#define PLW   76                 // G plane width (left/right zero borders)
#define PLH   65                 // G rows: iy+1 in [0,64]
#define PLANE (PLW*PLH)          // 4940 floats; 4940*4B % 16 == 0
#define SMF   (CH*PLANE)         // 19760 floats = 79,040 B
#define GPOS  (65*65)            // valid G positions per channel
#define NVEC  (CH*PLH*4)         // border float4 zeros: 4 planes * 65 rows * 4 vecs

// out[b,y,x] = sum_c bilinear(patch_c centered, y-64-dy_c, x-64-dx_c), zero fill.
// Integer pixel coords => fractional bilinear weights constant per (b,c), so
// out(y,x) = G_c[y+oyc][x+oxc] with G_c = 2x2 correlation of patch_c and the
// weights. G built once per sample in smem; eval = one aligned LDS.128/channel.
__global__ __launch_bounds__(TPB, 2)
void reassemble_conv1_kernel(const float* __restrict__ patches,
                             const float* __restrict__ pos,
                             float* __restrict__ out)
{
    extern __shared__ float sm[];        // CH planes of [PLH][PLW]
    const int b   = blockIdx.x;
    const int tid = threadIdx.x;

    // ---- per-channel constants ----
    int   oxc[CH], shf[CH], off0[CH], ylo[CH];
    float w00[CH], w01[CH], w10[CH], w11[CH];
    const float* pb_pos = pos + (size_t)b * 2 * CH;
    #pragma unroll
    for (int c = 0; c < CH; c++) {
        const float dx = __ldg(pb_pos + c);
        const float dy = __ldg(pb_pos + CH + c);
        const float fx = -64.0f - dx;
        const float fy = -64.0f - dy;
        const float flx = floorf(fx), fly = floorf(fy);
        oxc[c] = (int)flx;
        const int oy = (int)fly;
        shf[c] = (4 - (oxc[c] & 3)) & 3;             // (oxc+shf) % 4 == 0
        // eval smem offset: off0 + y*PLW + x0, valid iff checks pass
        off0[c] = c * PLANE + (oy + 1) * PLW + oxc[c] + shf[c] + 4;
        ylo[c]  = oy;                                 // iy = y + oy
        const float wx = fx - flx, wy = fy - fly;
        w00[c] = (1.0f - wx) * (1.0f - wy);
        w01[c] = wx * (1.0f - wy);
        w10[c] = (1.0f - wx) * wy;
        w11[c] = wx * wy;
    }

    // ---- zero only the left/right border columns (cols 0..7 and 68..75) ----
    {
        float4* smv = reinterpret_cast<float4*>(sm);
        #pragma unroll
        for (int i = tid; i < NVEC; i += TPB) {       // 1040 vecs -> ~2 iters
            const int pl  = i >> 8;                   // /260? no: use exact below
            // exact decode: per plane 65*4 = 260 vecs
            const int plane = i / 260;
            const int rem   = i - plane * 260;
            const int row   = rem >> 2;
            const int v     = rem & 3;
            const int col4  = (v < 2) ? (v << 2) : (68 + ((v - 2) << 2));
            smv[(plane * PLANE + row * PLW + col4) >> 2] = make_float4(0.f, 0.f, 0.f, 0.f);
            (void)pl;
        }
    }
    __syncthreads();

    // ---- build G planes from global (pixel-major float4 taps) ----
    const float4* pin = reinterpret_cast<const float4*>(patches + (size_t)b * NP * NP * CH);
    for (int idx = tid; idx < GPOS; idx += TPB) {     // ~8.25 iters
        const int gy  = idx / 65;
        const int gxi = idx - gy * 65;
        const int iy  = gy - 1;
        const int ix  = gxi - 1;

        const bool r0 = (gy >= 1), r1 = (gy <= 63);
        const bool c0 = (gxi >= 1), c1 = (gxi <= 63);
        const float4 z = make_float4(0.f, 0.f, 0.f, 0.f);
        const float4 t00 = (r0 && c0) ? __ldg(pin + iy * NP + ix)     : z;
        const float4 t01 = (r0 && c1) ? __ldg(pin + iy * NP + ix + 1) : z;
        const float4 t10 = (r1 && c0) ? __ldg(pin + gy * NP + ix)     : z;
        const float4 t11 = (r1 && c1) ? __ldg(pin + gy * NP + ix + 1) : z;

        const int rb = gy * PLW + gxi + 3;
        sm[0 * PLANE + rb + shf[0]] = t00.x * w00[0] + t01.x * w01[0] + t10.x * w10[0] + t11.x * w11[0];
        sm[1 * PLANE + rb + shf[1]] = t00.y * w00[1] + t01.y * w01[1] + t10.y * w10[1] + t11.y * w11[1];
        sm[2 * PLANE + rb + shf[2]] = t00.z * w00[2] + t01.z * w01[2] + t10.z * w10[2] + t11.z * w11[2];
        sm[3 * PLANE + rb + shf[3]] = t00.w * w00[3] + t01.w * w01[3] + t10.w * w10[3] + t11.w * w11[3];
    }
    __syncthreads();

    // ---- eval: full canvas, 4 consecutive x per thread, float4 store ----
    float* ob = out + (size_t)b * PAD * PAD;

    #pragma unroll 6
    for (int q = 0; q < (PAD * PAD / 4) / TPB; q++) {  // 18 iters
        const int p   = q * TPB + tid;                 // 0..9215
        const int y   = p / (PAD / 4);                 // /48 (mul-shift)
        const int x0  = (p - y * (PAD / 4)) * 4;
        const int yw  = y * PLW;

        float a0 = 0.f, a1 = 0.f, a2 = 0.f, a3 = 0.f;

        #pragma unroll
        for (int c = 0; c < CH; c++) {
            const int iy = y + ylo[c];
            if ((unsigned)(iy + 1) > 64u) continue;    // iy outside [-1,63]
            const int ix0 = x0 + oxc[c];
            if ((unsigned)(ix0 + 4) > 67u) continue;   // ix0 outside [-4,63]

            const float4 g = *reinterpret_cast<const float4*>(sm + off0[c] + yw + x0);
            a0 += g.x; a1 += g.y; a2 += g.z; a3 += g.w;
        }

        float4 o4; o4.x = a0; o4.y = a1; o4.z = a2; o4.w = a3;
        *reinterpret_cast<float4*>(ob + (size_t)y * PAD + x0) = o4;
    }
}

extern "C" void kernel_launch(void* const* d_in, const int* in_sizes, int n_in,
                              void* d_out, int out_size) {
    const float* patches = (const float*)d_in[0];   // (B, 64, 64, 4) fp32
    const float* pos     = (const float*)d_in[1];   // (B, 1, 2, 4)  fp32
    float* out           = (float*)d_out;           // (B, 192, 192, 1) fp32

    const int B = out_size / (PAD * PAD);           // 512
    const int smem_bytes = SMF * sizeof(float);     // 79,040 B
    static bool attr_set = false;
    if (!attr_set) {
        cudaFuncSetAttribute(reassemble_conv1_kernel,
                             cudaFuncAttributeMaxDynamicSharedMemorySize, smem_bytes);
        attr_set = true;
    }
    reassemble_conv1_kernel<<<B, TPB, smem_bytes>>>(patches, pos, out);
}